// round 17
// baseline (speedup 1.0000x reference)
#include <cuda_runtime.h>
#include <cuda_fp16.h>
#include <math.h>

constexpr int NN = 50000;   // nodes
constexpr int HH = 16;      // hidden
constexpr int RR = 32;      // relations
constexpr int CC = 8;       // classes
constexpr int RN = RR * NN; // segments
constexpr int EMAX = 1600000;
constexpr int SBS  = 512;                  // source-block size for locality binning
constexpr int NSB  = (NN + SBS - 1) / SBS; // 98 source blocks
constexpr int NBINS = RR * NSB;            // 3136 bins, r-major

// Scratch (device globals: no allocation allowed).
// g_cnt invariant: zero at kernel_launch entry (zero-init at load; re-zeroed by k_l1).
__device__ int                g_cnt[RN];     // edge counts per (rel,dst)
__device__ float              g_x[NN * HH];  // layer-1 node features (fp32)
__device__ __align__(16) __half g_xh[NN * HH]; // fp16 copy for layer-2 gather
__device__ __align__(16) unsigned long long g_pk[EMAX + 4]; // s | d<<16 | r<<32 | c<<40
__device__ int                g_hist[NBINS]; // bin histogram (re-zeroed by k_scan)
__device__ int                g_cursor[NBINS]; // scatter cursors

// ---------------------------------------------------------------------------
// 0) zero g_x/out + (r, s-block) bin histogram + (rel,dst) segment counts (2 edges/thread)
__global__ void k_init_hist(const int* __restrict__ et, const int* __restrict__ srcv,
                            const int* __restrict__ dstv, float* __restrict__ out, int E) {
    __shared__ int sh[NBINS];
    int t = threadIdx.x;
    for (int j = t; j < NBINS; j += blockDim.x) sh[j] = 0;
    __syncthreads();
    int i = blockIdx.x * blockDim.x + t;
    if (i < NN * HH) g_x[i] = 0.0f;
    if (i < NN * CC) out[i] = 0.0f;
    int e0 = 2 * i;
    if (e0 < E) {
        int2 rr2 = *(const int2*)(et + e0);
        int2 ss2 = *(const int2*)(srcv + e0);
        int2 dd2 = *(const int2*)(dstv + e0);
        atomicAdd(&sh[rr2.x * NSB + (ss2.x >> 9)], 1);
        atomicAdd(&g_cnt[rr2.x * NN + dd2.x], 1);
        if (e0 + 1 < E) {
            atomicAdd(&sh[rr2.y * NSB + (ss2.y >> 9)], 1);
            atomicAdd(&g_cnt[rr2.y * NN + dd2.y], 1);
        }
    }
    __syncthreads();
    for (int j = t; j < NBINS; j += blockDim.x) {
        int v = sh[j];
        if (v) atomicAdd(&g_hist[j], v);
    }
}

// 1) exclusive scan of NBINS histogram -> cursors; re-zero g_hist for next replay
//    single block, 1024 threads, 4 elements per thread
__global__ void k_scan() {
    __shared__ int stot[1024];
    int t = threadIdx.x;
    int base = t * 4;
    int v[4] = {0, 0, 0, 0};
    int tot = 0;
#pragma unroll
    for (int k = 0; k < 4; k++) {
        int j = base + k;
        if (j < NBINS) { v[k] = g_hist[j]; tot += v[k]; }
    }
    stot[t] = tot;
    __syncthreads();
    // Hillis-Steele inclusive scan over 1024 totals
    for (int o = 1; o < 1024; o <<= 1) {
        int a = (t >= o) ? stot[t - o] : 0;
        __syncthreads();
        stot[t] += a;
        __syncthreads();
    }
    int run = stot[t] - tot;   // exclusive prefix of this thread's chunk
#pragma unroll
    for (int k = 0; k < 4; k++) {
        int j = base + k;
        if (j < NBINS) {
            g_cursor[j] = run;
            g_hist[j] = 0;
            run += v[k];
        }
    }
}

// 2) scatter edges into (r, s-block)-sorted packed array;
//    bakes the (final) segment count into the edge word.
__global__ void k_scatter(const int* __restrict__ et, const int* __restrict__ srcv,
                          const int* __restrict__ dstv, int E) {
    __shared__ int sh[NBINS];     // per-block bin sizes / ranks
    __shared__ int sbase[NBINS];  // per-block bin bases
    int t = threadIdx.x;
    for (int j = t; j < NBINS; j += blockDim.x) sh[j] = 0;
    __syncthreads();

    int e = blockIdx.x * blockDim.x + t;
    bool ok = e < E;
    int r = 0, s = 0, d = 0, b = 0, rank = 0;
    if (ok) {
        r = et[e]; s = srcv[e]; d = dstv[e];
        b = r * NSB + (s >> 9);
        rank = atomicAdd(&sh[b], 1);
    }
    __syncthreads();
    for (int j = t; j < NBINS; j += blockDim.x)
        sbase[j] = sh[j] ? atomicAdd(&g_cursor[j], sh[j]) : 0;
    __syncthreads();

    if (ok) {
        unsigned c = (unsigned)__ldg(&g_cnt[r * NN + d]);   // final count
        g_pk[sbase[b] + rank] = (unsigned long long)(unsigned)s
                              | ((unsigned long long)(unsigned)d << 16)
                              | ((unsigned long long)(unsigned)r << 32)
                              | ((unsigned long long)c << 40);
    }
}

// 3) layer-1 scatter: x[d] += (1/c) * w1[r,s]
//    2 edges per 4-lane group (ulonglong2); count decoded from edge word.
//    Also re-zeroes g_cnt (coalesced; restores the replay invariant).
__global__ void k_l1(const float* __restrict__ w1, int E) {
    int idx = blockIdx.x * blockDim.x + threadIdx.x;
    if (idx < RN) g_cnt[idx] = 0;                 // fold re-zeroing into this pass

    int g = idx >> 2, q = idx & 3;
    int e0 = 2 * g;
    if (e0 >= E) return;
    bool ok1 = (e0 + 1) < E;

    ulonglong2 pv = __ldg(((const ulonglong2*)g_pk) + g);
    unsigned long long p0 = pv.x, p1 = pv.y;

    int s0 = (int)(p0 & 0xFFFFu), d0 = (int)((p0 >> 16) & 0xFFFFu);
    int r0 = (int)((p0 >> 32) & 0xFFu), c0 = (int)((p0 >> 40) & 0xFFFFu);
    int s1 = (int)(p1 & 0xFFFFu), d1 = (int)((p1 >> 16) & 0xFFFFu);
    int r1 = (int)((p1 >> 32) & 0xFFu), c1 = (int)((p1 >> 40) & 0xFFFFu);

    const float4 w0 = __ldg(((const float4*)(w1 + ((long)(r0 * NN + s0) << 4))) + q);
    float4 w1v = make_float4(0.f, 0.f, 0.f, 0.f);
    if (ok1) w1v = __ldg(((const float4*)(w1 + ((long)(r1 * NN + s1) << 4))) + q);

    float i0 = __fdividef(1.0f, (float)(c0 > 0 ? c0 : 1));
    float i1 = ok1 ? __fdividef(1.0f, (float)(c1 > 0 ? c1 : 1)) : 0.0f;

    float* pd0 = &g_x[d0 * HH + q * 4];
    asm volatile("red.global.add.v4.f32 [%0], {%1,%2,%3,%4};"
                 :: "l"(pd0), "f"(w0.x * i0), "f"(w0.y * i0),
                    "f"(w0.z * i0), "f"(w0.w * i0) : "memory");
    if (ok1) {
        float* pd1 = &g_x[d1 * HH + q * 4];
        asm volatile("red.global.add.v4.f32 [%0], {%1,%2,%3,%4};"
                     :: "l"(pd1), "f"(w1v.x * i1), "f"(w1v.y * i1),
                        "f"(w1v.z * i1), "f"(w1v.w * i1) : "memory");
    }
}

// 4) x = relu(x + root1 + b1)  (float4); also writes fp16 copy for l2 gather
__global__ void k_relu(const float4* __restrict__ root1, const float* __restrict__ b1) {
    int i = blockIdx.x * blockDim.x + threadIdx.x;
    if (i >= NN * HH / 4) return;
    float4 v = ((float4*)g_x)[i];
    float4 rr = __ldg(root1 + i);
    int q = (i & 3) * 4;
    v.x += rr.x + b1[q];
    v.y += rr.y + b1[q + 1];
    v.z += rr.z + b1[q + 2];
    v.w += rr.w + b1[q + 3];
    v.x = fmaxf(v.x, 0.f); v.y = fmaxf(v.y, 0.f);
    v.z = fmaxf(v.z, 0.f); v.w = fmaxf(v.w, 0.f);
    ((float4*)g_x)[i] = v;
    __half2 h0 = __floats2half2_rn(v.x, v.y);
    __half2 h1 = __floats2half2_rn(v.z, v.w);
    ((__half2*)g_xh)[2 * i]     = h0;
    ((__half2*)g_xh)[2 * i + 1] = h1;
}

// 5) layer-2 scatter: out[d] += (1/c) * (x[s] @ w2[r])
//    2 edges per thread (ulonglong2 pk + 4 fp16 x loads in flight); fp32 math.
__global__ void __launch_bounds__(256) k_l2(const float* __restrict__ w2,
                                            float* __restrict__ out, int E) {
    __shared__ float s_w2[RR * HH * CC];   // 16 KB
    for (int i = threadIdx.x; i < RR * HH * CC; i += blockDim.x) s_w2[i] = w2[i];
    __syncthreads();

    int P = (E + 1) >> 1;
    int stride = gridDim.x * blockDim.x;
    const ulonglong2* pk2 = (const ulonglong2*)g_pk;

    for (int g = blockIdx.x * blockDim.x + threadIdx.x; g < P; g += stride) {
        ulonglong2 pv = __ldg(pk2 + g);
        bool ok1 = (2 * g + 1) < E;

        int s0 = (int)(pv.x & 0xFFFFu), d0 = (int)((pv.x >> 16) & 0xFFFFu);
        int r0 = (int)((pv.x >> 32) & 0xFFu), c0 = (int)((pv.x >> 40) & 0xFFFFu);
        int s1 = (int)(pv.y & 0xFFFFu), d1 = (int)((pv.y >> 16) & 0xFFFFu);
        int r1 = (int)((pv.y >> 32) & 0xFFu), c1 = (int)((pv.y >> 40) & 0xFFFFu);
        if (!ok1) { s1 = s0; r1 = r0; }

        const uint4* xr0 = (const uint4*)(g_xh + s0 * HH);
        const uint4* xr1 = (const uint4*)(g_xh + s1 * HH);
        uint4 hA0 = __ldg(xr0), hB0 = __ldg(xr0 + 1);
        uint4 hA1 = __ldg(xr1), hB1 = __ldg(xr1 + 1);

        float i0 = __fdividef(1.0f, (float)(c0 > 0 ? c0 : 1));
        float i1 = __fdividef(1.0f, (float)(c1 > 0 ? c1 : 1));

        const float* wr0 = s_w2 + r0 * HH * CC;
        const float* wr1 = s_w2 + r1 * HH * CC;

        float y0[CC] = {0,0,0,0,0,0,0,0};
        float y1[CC] = {0,0,0,0,0,0,0,0};
        {
            const unsigned* ha0 = (const unsigned*)&hA0;
            const unsigned* hb0 = (const unsigned*)&hB0;
            const unsigned* ha1 = (const unsigned*)&hA1;
            const unsigned* hb1 = (const unsigned*)&hB1;
#pragma unroll
            for (int hp = 0; hp < 8; hp++) {
                unsigned u0 = (hp < 4) ? ha0[hp] : hb0[hp - 4];
                unsigned u1 = (hp < 4) ? ha1[hp] : hb1[hp - 4];
                float2 f0 = __half22float2(*(const __half2*)&u0);
                float2 f1 = __half22float2(*(const __half2*)&u1);
                const float* wa = wr0 + (2 * hp) * CC;
                const float* wb = wr1 + (2 * hp) * CC;
#pragma unroll
                for (int c = 0; c < CC; c++) {
                    y0[c] += f0.x * wa[c] + f0.y * wa[CC + c];
                    y1[c] += f1.x * wb[c] + f1.y * wb[CC + c];
                }
            }
        }

        float* pd0 = out + d0 * CC;
        asm volatile("red.global.add.v4.f32 [%0], {%1,%2,%3,%4};"
                     :: "l"(pd0), "f"(y0[0] * i0), "f"(y0[1] * i0),
                        "f"(y0[2] * i0), "f"(y0[3] * i0) : "memory");
        asm volatile("red.global.add.v4.f32 [%0], {%1,%2,%3,%4};"
                     :: "l"(pd0 + 4), "f"(y0[4] * i0), "f"(y0[5] * i0),
                        "f"(y0[6] * i0), "f"(y0[7] * i0) : "memory");
        if (ok1) {
            float* pd1 = out + d1 * CC;
            asm volatile("red.global.add.v4.f32 [%0], {%1,%2,%3,%4};"
                         :: "l"(pd1), "f"(y1[0] * i1), "f"(y1[1] * i1),
                            "f"(y1[2] * i1), "f"(y1[3] * i1) : "memory");
            asm volatile("red.global.add.v4.f32 [%0], {%1,%2,%3,%4};"
                         :: "l"(pd1 + 4), "f"(y1[4] * i1), "f"(y1[5] * i1),
                            "f"(y1[6] * i1), "f"(y1[7] * i1) : "memory");
        }
    }
}

// 6) finalize: out = log_softmax(out + x @ root2 + b2)   (fp32 x)
__global__ void k_fin(const float* __restrict__ root2, const float* __restrict__ b2,
                      float* __restrict__ out) {
    __shared__ float s_r2[HH * CC];
    __shared__ float s_b2[CC];
    for (int i = threadIdx.x; i < HH * CC; i += blockDim.x) s_r2[i] = root2[i];
    if (threadIdx.x < CC) s_b2[threadIdx.x] = b2[threadIdx.x];
    __syncthreads();

    int n = blockIdx.x * blockDim.x + threadIdx.x;
    if (n >= NN) return;

    float y[CC];
    float4 a0 = *(const float4*)(out + n * CC);
    float4 a1 = *(const float4*)(out + n * CC + 4);
    y[0] = a0.x; y[1] = a0.y; y[2] = a0.z; y[3] = a0.w;
    y[4] = a1.x; y[5] = a1.y; y[6] = a1.z; y[7] = a1.w;

#pragma unroll
    for (int h = 0; h < HH; h++) {
        float xv = g_x[n * HH + h];
#pragma unroll
        for (int c = 0; c < CC; c++) y[c] += xv * s_r2[h * CC + c];
    }
#pragma unroll
    for (int c = 0; c < CC; c++) y[c] += s_b2[c];

    float m = y[0];
#pragma unroll
    for (int c = 1; c < CC; c++) m = fmaxf(m, y[c]);
    float sum = 0.0f;
#pragma unroll
    for (int c = 0; c < CC; c++) sum += __expf(y[c] - m);
    float l = m + logf(sum);
#pragma unroll
    for (int c = 0; c < CC; c++) out[n * CC + c] = y[c] - l;
}

// ---------------------------------------------------------------------------
extern "C" void kernel_launch(void* const* d_in, const int* in_sizes, int n_in,
                              void* d_out, int out_size) {
    const int*   ei    = (const int*)d_in[0];     // [2, E]
    const int*   et    = (const int*)d_in[1];     // [E]
    const float* w1    = (const float*)d_in[2];   // [R, N, H]
    const float* root1 = (const float*)d_in[3];   // [N, H]
    const float* b1    = (const float*)d_in[4];   // [H]
    const float* w2    = (const float*)d_in[5];   // [R, H, C]
    const float* root2 = (const float*)d_in[6];   // [H, C]
    const float* b2    = (const float*)d_in[7];   // [C]
    float* out = (float*)d_out;

    const int E = in_sizes[0] / 2;
    const int* srcv = ei;
    const int* dstv = ei + E;

    const int T = 256;
    k_init_hist <<<(NN * HH + T - 1) / T, T>>> (et, srcv, dstv, out, E);
    k_scan      <<<1, 1024>>> ();
    k_scatter   <<<(E + T - 1) / T, T>>> (et, srcv, dstv, E);
    int pairs = (E + 1) / 2;
    int l1threads = 4 * pairs > RN ? 4 * pairs : RN;
    k_l1        <<<(l1threads + T - 1) / T, T>>> (w1, E);
    k_relu      <<<(NN * HH / 4 + T - 1) / T, T>>> ((const float4*)root1, b1);
    k_l2        <<<1184, T>>> (w2, out, E);
    k_fin       <<<(NN + T - 1) / T, T>>> (root2, b2, out);
}